// round 6
// baseline (speedup 1.0000x reference)
#include <cuda_runtime.h>
#include <cuda_bf16.h>
#include <cstdint>
#include <math.h>

// ---------------- problem dims ----------------
#define SEQ   512
#define BATCH 64
#define INPUT 256
#define HID   1024

// ---------------- config ----------------
#define NCTA  128            // 16 m-tiles x 8 k-slices
#define NTHR  256
#define NM    16
#define NKS   8
#define RPC   256            // rows per CTA (4 gates x 64 j)
#define ASTR  336            // smem row stride bytes (160*2 + 16 pad)
#define OFF_AHI 0
#define OFF_ALO (RPC*ASTR)
#define OFF_BHI (2*RPC*ASTR)
#define OFF_BLO (2*RPC*ASTR + BATCH*ASTR)
#define SMEM_TOTAL (2*RPC*ASTR + 2*BATCH*ASTR) // 215040

// ---------------- scratch ----------------
__device__ __align__(16) __nv_bfloat16 g_hhi[2 * BATCH * HID];   // double buffer
__device__ __align__(16) __nv_bfloat16 g_hlo[2 * BATCH * HID];
__device__ __align__(16) __nv_bfloat16 g_xhi[(size_t)SEQ * BATCH * INPUT];
__device__ __align__(16) __nv_bfloat16 g_xlo[(size_t)SEQ * BATCH * INPUT];
__device__ float    g_part[NKS * NM * RPC * BATCH];  // [ks][m][row][b]
__device__ unsigned g_bar;                           // global barrier counter
__device__ unsigned g_barm[NM * 32];                 // per-m-tile counters, 128B apart

struct Params {
    const float* x;
    const float* Wx[4]; const float* bx[4];
    const float* Wh[4]; const float* bh[4];
    float* out;
};

// ---------------- helpers ----------------
__device__ __forceinline__ uint32_t smem_u32(const void* p) {
    uint32_t a;
    asm("{ .reg .u64 t; cvta.to.shared.u64 t, %1; cvt.u32.u64 %0, t; }" : "=r"(a) : "l"(p));
    return a;
}
__device__ __forceinline__ void ldsm4(uint32_t* r, uint32_t addr) {
    asm volatile("ldmatrix.sync.aligned.m8n8.x4.shared.b16 {%0,%1,%2,%3}, [%4];"
        : "=r"(r[0]), "=r"(r[1]), "=r"(r[2]), "=r"(r[3]) : "r"(addr));
}
__device__ __forceinline__ void ldsm2(uint32_t* r, uint32_t addr) {
    asm volatile("ldmatrix.sync.aligned.m8n8.x2.shared.b16 {%0,%1}, [%2];"
        : "=r"(r[0]), "=r"(r[1]) : "r"(addr));
}
__device__ __forceinline__ void mma_bf16(float* d, const uint32_t* a, const uint32_t* b) {
    asm volatile(
        "mma.sync.aligned.m16n8k16.row.col.f32.bf16.bf16.f32 "
        "{%0,%1,%2,%3}, {%4,%5,%6,%7}, {%8,%9}, {%0,%1,%2,%3};"
        : "+f"(d[0]), "+f"(d[1]), "+f"(d[2]), "+f"(d[3])
        : "r"(a[0]), "r"(a[1]), "r"(a[2]), "r"(a[3]), "r"(b[0]), "r"(b[1]));
}
__device__ __forceinline__ void split2(float va, float vb, uint32_t& hi, uint32_t& lo) {
    __nv_bfloat16 ha = __float2bfloat16_rn(va);
    __nv_bfloat16 hb = __float2bfloat16_rn(vb);
    float ra = va - __bfloat162float(ha);
    float rb = vb - __bfloat162float(hb);
    __nv_bfloat162 hp; hp.x = ha; hp.y = hb;
    __nv_bfloat162 lp; lp.x = __float2bfloat16_rn(ra); lp.y = __float2bfloat16_rn(rb);
    hi = *(uint32_t*)&hp;
    lo = *(uint32_t*)&lp;
}
__device__ __forceinline__ float sigm(float x) { return 1.0f / (1.0f + __expf(-x)); }

// group barrier: syncs the 8 k-slice CTAs of one m-tile (private counter line)
__device__ __forceinline__ void group_barrier(int mcta, unsigned target) {
    __threadfence();                  // release partial stores (all threads)
    __syncthreads();
    if (threadIdx.x == 0) {
        volatile unsigned* c = &g_barm[mcta * 32];
        atomicAdd((unsigned*)c, 1u);
        while (*c < target) { }
        __threadfence();
    }
    __syncthreads();
}

// global barrier: contended counter + single-line poll (R3-proven)
__device__ __forceinline__ void grid_barrier(unsigned target) {
    __threadfence();                  // release h stores (all threads)
    __syncthreads();
    if (threadIdx.x == 0) {
        atomicAdd(&g_bar, 1u);
        while (*((volatile unsigned*)&g_bar) < target) __nanosleep(16);
        __threadfence();
    }
    __syncthreads();
}

// ---------------------------------------------------------------------------
// init: split x to bf16 hi/lo, zero h buffers, reset counters
__global__ void init_kernel(const float* __restrict__ x) {
    size_t i = (size_t)blockIdx.x * blockDim.x + threadIdx.x;
    if (i < (size_t)SEQ * BATCH * INPUT / 4) {
        float4 v = ((const float4*)x)[i];
        uint32_t h0, l0, h1, l1;
        split2(v.x, v.y, h0, l0);
        split2(v.z, v.w, h1, l1);
        ((uint2*)g_xhi)[i] = make_uint2(h0, h1);
        ((uint2*)g_xlo)[i] = make_uint2(l0, l1);
    }
    if (i < 2 * BATCH * HID * 2 / 8) {            // uint2 = 4 bf16
        ((uint2*)g_hhi)[i] = make_uint2(0u, 0u);
        ((uint2*)g_hlo)[i] = make_uint2(0u, 0u);
    }
    if (i < NM * 32) g_barm[i] = 0u;
    if (i == 0) g_bar = 0u;
}

// ---------------------------------------------------------------------------
__global__ __launch_bounds__(NTHR, 1)
void lstm_mma(Params P) {
    extern __shared__ char smem[];
    const uint32_t sb = smem_u32(smem);

    const int tid  = threadIdx.x;
    const int w    = tid >> 5;
    const int l    = tid & 31;
    const int mcta = blockIdx.x >> 3;   // 0..15
    const int ks   = blockIdx.x & 7;    // 0..7
    const int j0   = mcta * 64;

    // ---- stage weights into smem (hi/lo bf16), once per launch ----
    {
        const int r = tid;
        const int gate = r >> 6, jl = r & 63, j = j0 + jl;
        const float4* wh = (const float4*)(P.Wh[gate] + (size_t)j * HID + ks * 128);
        const float4* wx = (const float4*)(P.Wx[gate] + (size_t)j * INPUT + ks * 32);
        char* ahi = smem + OFF_AHI + r * ASTR;
        char* alo = smem + OFF_ALO + r * ASTR;
        #pragma unroll 4
        for (int f = 0; f < 40; f++) {
            float4 v = (f < 32) ? wh[f] : wx[f - 32];
            uint32_t h0, l0, h1, l1;
            split2(v.x, v.y, h0, l0);
            split2(v.z, v.w, h1, l1);
            *(uint2*)(ahi + f * 8) = make_uint2(h0, h1);
            *(uint2*)(alo + f * 8) = make_uint2(l0, l1);
        }
    }

    // ---- ldmatrix lane addresses ----
    const uint32_t a_row = (uint32_t)(w * 32 + (l & 7) + ((l >> 3) & 1) * 8);
    const uint32_t a_colb = (uint32_t)(((l >> 4) & 1) * 16);
    const uint32_t aAddrHi0 = sb + OFF_AHI + a_row * ASTR + a_colb;
    const uint32_t aAddrHi1 = aAddrHi0 + 16 * ASTR;
    const uint32_t aAddrLo0 = aAddrHi0 + (OFF_ALO - OFF_AHI);
    const uint32_t aAddrLo1 = aAddrLo0 + 16 * ASTR;
    const uint32_t b_rowb = (uint32_t)((l & 7) * ASTR);
    const uint32_t b_colb = (uint32_t)(((l >> 3) & 1) * 16);
    const uint32_t bAddrHi = sb + OFF_BHI + b_rowb + b_colb;
    const uint32_t bAddrLo = bAddrHi + (OFF_BLO - OFF_BHI);

    // ---- pointwise cell ownership: 2 cells per thread ----
    const int pb  = ks * 8 + (tid & 7);
    const int jlA = tid >> 3;
    const int jlB = jlA + 32;
    const int jA  = j0 + jlA, jB = j0 + jlB;
    float biasA[4], biasB[4];
    #pragma unroll
    for (int g = 0; g < 4; g++) {
        biasA[g] = P.bh[g][jA] + P.bx[g][jA];
        biasB[g] = P.bh[g][jB] + P.bx[g][jB];
    }
    float cA = 0.0f, cB = 0.0f;

    float* out = P.out;
    const size_t BH  = (size_t)BATCH * HID;
    const size_t SBH = (size_t)SEQ * BH;

    // staging index precompute
    const int stb = tid >> 2;           // batch 0..63
    const int stf = tid & 3;            // phase 0..3
    const size_t hoff = (size_t)stb * HID + ks * 128;
    char* bhi_row = smem + OFF_BHI + stb * ASTR;
    char* blo_row = smem + OFF_BLO + stb * ASTR;
    const size_t x_row_off = (size_t)stb * INPUT + ks * 32;

    float* ppart = g_part + (size_t)(ks * NM + mcta) * RPC * BATCH;

    // ---- pre-loop: stage x(0) and h(0) (buffer 0, zeros) ----
    {
        const uint4* xs = (const uint4*)(g_xhi + x_row_off);
        const uint4* xl = (const uint4*)(g_xlo + x_row_off);
        *(uint4*)(bhi_row + 256 + stf * 16) = __ldcg(xs + stf);
        *(uint4*)(blo_row + 256 + stf * 16) = __ldcg(xl + stf);
        const uint4* hhi_src = (const uint4*)(g_hhi + hoff);
        const uint4* hlo_src = (const uint4*)(g_hlo + hoff);
        #pragma unroll
        for (int q = 0; q < 4; q++) {
            int idx = stf + q * 4;
            *(uint4*)(bhi_row + idx * 16) = __ldcg(hhi_src + idx);
            *(uint4*)(blo_row + idx * 16) = __ldcg(hlo_src + idx);
        }
    }
    __syncthreads();

    for (int t = 0; t < SEQ; t++) {
        // ---- GEMM: D[256 rows][64 b], 3-pass split bf16 ----
        float d[2][8][4];
        #pragma unroll
        for (int mt = 0; mt < 2; mt++)
            #pragma unroll
            for (int nt = 0; nt < 8; nt++)
                #pragma unroll
                for (int q = 0; q < 4; q++) d[mt][nt][q] = 0.0f;

        for (int kt = 0; kt < 10; kt++) {
            const uint32_t kb = (uint32_t)(kt * 32);
            uint32_t Ah0[4], Ah1[4], Al0[4], Al1[4];
            ldsm4(Ah0, aAddrHi0 + kb);
            ldsm4(Ah1, aAddrHi1 + kb);
            ldsm4(Al0, aAddrLo0 + kb);
            ldsm4(Al1, aAddrLo1 + kb);
            #pragma unroll
            for (int nt = 0; nt < 8; nt++) {
                uint32_t Bh[2], Bl[2];
                const uint32_t bo = (uint32_t)(nt * 8 * ASTR) + kb;
                ldsm2(Bh, bAddrHi + bo);
                ldsm2(Bl, bAddrLo + bo);
                mma_bf16(d[0][nt], Ah0, Bh);
                mma_bf16(d[1][nt], Ah1, Bh);
                mma_bf16(d[0][nt], Ah0, Bl);
                mma_bf16(d[1][nt], Ah1, Bl);
                mma_bf16(d[0][nt], Al0, Bh);
                mma_bf16(d[1][nt], Al1, Bh);
            }
        }

        // ---- store partials [row][b] ----
        {
            const int r0 = w * 32 + (l >> 2);
            const int c0 = (l & 3) * 2;
            #pragma unroll
            for (int mt = 0; mt < 2; mt++) {
                #pragma unroll
                for (int nt = 0; nt < 8; nt++) {
                    int row = r0 + mt * 16;
                    int col = nt * 8 + c0;
                    *(float2*)(ppart + (size_t)row * BATCH + col) =
                        make_float2(d[mt][nt][0], d[mt][nt][1]);
                    *(float2*)(ppart + (size_t)(row + 8) * BATCH + col) =
                        make_float2(d[mt][nt][2], d[mt][nt][3]);
                }
            }
        }

        // ---- B smem GEMM reads done -> stage x(t+1) (overlaps bar1) ----
        __syncthreads();
        if (t + 1 < SEQ) {
            const size_t xo = (size_t)(t + 1) * BATCH * INPUT + x_row_off;
            const uint4* xs = (const uint4*)(g_xhi + xo);
            const uint4* xl = (const uint4*)(g_xlo + xo);
            *(uint4*)(bhi_row + 256 + stf * 16) = __ldcg(xs + stf);
            *(uint4*)(blo_row + 256 + stf * 16) = __ldcg(xl + stf);
        }

        // ---- bar1: group-local (8 CTAs of this m-tile) ----
        group_barrier(mcta, (unsigned)(t + 1) * NKS);

        // ---- reduce 8 k-slices + pointwise; h -> buf[(t+1)&1] ----
        {
            const size_t hw = (size_t)((t + 1) & 1) * BH;
            float accA[4], accB[4];
            #pragma unroll
            for (int g = 0; g < 4; g++) { accA[g] = biasA[g]; accB[g] = biasB[g]; }
            #pragma unroll
            for (int g = 0; g < 4; g++) {
                #pragma unroll
                for (int s = 0; s < NKS; s++) {
                    const float* pp = g_part + (size_t)(s * NM + mcta) * RPC * BATCH + pb;
                    accA[g] += __ldcg(pp + (size_t)(g * 64 + jlA) * BATCH);
                    accB[g] += __ldcg(pp + (size_t)(g * 64 + jlB) * BATCH);
                }
            }
            float f, i1, i2, o, hv;

            f = sigm(accA[0]); i1 = sigm(accA[1]); i2 = tanhf(accA[2]); o = sigm(accA[3]);
            cA = cA * f + i1 * i2;
            hv = tanhf(cA) * o;
            out[(size_t)t * BH + (size_t)pb * HID + jA] = hv;
            {
                __nv_bfloat16 hb = __float2bfloat16_rn(hv);
                g_hhi[hw + (size_t)pb * HID + jA] = hb;
                g_hlo[hw + (size_t)pb * HID + jA] = __float2bfloat16_rn(hv - __bfloat162float(hb));
            }
            if (t == SEQ - 1) {
                out[SBH + (size_t)pb * HID + jA] = hv;
                out[SBH + BH + (size_t)pb * HID + jA] = cA;
            }

            f = sigm(accB[0]); i1 = sigm(accB[1]); i2 = tanhf(accB[2]); o = sigm(accB[3]);
            cB = cB * f + i1 * i2;
            hv = tanhf(cB) * o;
            out[(size_t)t * BH + (size_t)pb * HID + jB] = hv;
            {
                __nv_bfloat16 hb = __float2bfloat16_rn(hv);
                g_hhi[hw + (size_t)pb * HID + jB] = hb;
                g_hlo[hw + (size_t)pb * HID + jB] = __float2bfloat16_rn(hv - __bfloat162float(hb));
            }
            if (t == SEQ - 1) {
                out[SBH + (size_t)pb * HID + jB] = hv;
                out[SBH + BH + (size_t)pb * HID + jB] = cB;
            }
        }

        // ---- bar2: global (h visibility) ----
        grid_barrier((unsigned)(t + 1) * NCTA);

        // ---- stage h(t+1) from buf[(t+1)&1] ----
        if (t + 1 < SEQ) {
            const size_t hr = (size_t)((t + 1) & 1) * BH + hoff;
            const uint4* hhi_src = (const uint4*)(g_hhi + hr);
            const uint4* hlo_src = (const uint4*)(g_hlo + hr);
            #pragma unroll
            for (int q = 0; q < 4; q++) {
                int idx = stf + q * 4;
                *(uint4*)(bhi_row + idx * 16) = __ldcg(hhi_src + idx);
                *(uint4*)(blo_row + idx * 16) = __ldcg(hlo_src + idx);
            }
            __syncthreads();
        }
    }
}

// ---------------------------------------------------------------------------
extern "C" void kernel_launch(void* const* d_in, const int* in_sizes, int n_in,
                              void* d_out, int out_size) {
    Params P;
    P.x = (const float*)d_in[0];
    P.Wx[0] = (const float*)d_in[1];  P.bx[0] = (const float*)d_in[2];
    P.Wx[1] = (const float*)d_in[3];  P.bx[1] = (const float*)d_in[4];
    P.Wx[2] = (const float*)d_in[5];  P.bx[2] = (const float*)d_in[6];
    P.Wx[3] = (const float*)d_in[7];  P.bx[3] = (const float*)d_in[8];
    P.Wh[0] = (const float*)d_in[9];  P.bh[0] = (const float*)d_in[10];
    P.Wh[1] = (const float*)d_in[11]; P.bh[1] = (const float*)d_in[12];
    P.Wh[2] = (const float*)d_in[13]; P.bh[2] = (const float*)d_in[14];
    P.Wh[3] = (const float*)d_in[15]; P.bh[3] = (const float*)d_in[16];
    P.out   = (float*)d_out;

    static bool attr_set = false;
    if (!attr_set) {
        cudaFuncSetAttribute(lstm_mma, cudaFuncAttributeMaxDynamicSharedMemorySize,
                             SMEM_TOTAL);
        attr_set = true;
    }

    init_kernel<<<(SEQ * BATCH * INPUT / 4 + 255) / 256, 256>>>(P.x);
    lstm_mma<<<NCTA, NTHR, SMEM_TOTAL>>>(P);
}

// round 7
// speedup vs baseline: 1.3421x; 1.3421x over previous
#include <cuda_runtime.h>
#include <cuda_bf16.h>
#include <cstdint>
#include <math.h>

// ---------------- problem dims ----------------
#define SEQ   512
#define BATCH 64
#define INPUT 256
#define HID   1024

// ---------------- config ----------------
#define NCTA  128            // 16 m-tiles x 8 k-slices
#define NTHR  256
#define NM    16
#define NKS   8
#define RPC   256            // rows per CTA (4 gates x 64 j)
#define ASTR  336            // smem row stride bytes (160*2 + 16 pad)
#define OFF_AHI 0
#define OFF_ALO (RPC*ASTR)
#define OFF_BHI (2*RPC*ASTR)
#define OFF_BLO (2*RPC*ASTR + BATCH*ASTR)
#define SMEM_TOTAL (2*RPC*ASTR + 2*BATCH*ASTR) // 215040

// ---------------- scratch ----------------
__device__ __align__(16) __nv_bfloat16 g_hhi[2 * BATCH * HID];   // double buffer
__device__ __align__(16) __nv_bfloat16 g_hlo[2 * BATCH * HID];
__device__ __align__(16) __nv_bfloat16 g_xhi[(size_t)SEQ * BATCH * INPUT];
__device__ __align__(16) __nv_bfloat16 g_xlo[(size_t)SEQ * BATCH * INPUT];
__device__ float    g_part[NKS * NM * RPC * BATCH];  // [ks][m][row][b]
__device__ unsigned g_bar;                           // global counter (16 leader arrivals/step)
__device__ unsigned g_grp[NM * 64];                  // per-group counters, 256B apart

struct Params {
    const float* x;
    const float* Wx[4]; const float* bx[4];
    const float* Wh[4]; const float* bh[4];
    float* out;
};

// ---------------- helpers ----------------
__device__ __forceinline__ uint32_t smem_u32(const void* p) {
    uint32_t a;
    asm("{ .reg .u64 t; cvta.to.shared.u64 t, %1; cvt.u32.u64 %0, t; }" : "=r"(a) : "l"(p));
    return a;
}
__device__ __forceinline__ void ldsm4(uint32_t* r, uint32_t addr) {
    asm volatile("ldmatrix.sync.aligned.m8n8.x4.shared.b16 {%0,%1,%2,%3}, [%4];"
        : "=r"(r[0]), "=r"(r[1]), "=r"(r[2]), "=r"(r[3]) : "r"(addr));
}
__device__ __forceinline__ void ldsm2(uint32_t* r, uint32_t addr) {
    asm volatile("ldmatrix.sync.aligned.m8n8.x2.shared.b16 {%0,%1}, [%2];"
        : "=r"(r[0]), "=r"(r[1]) : "r"(addr));
}
__device__ __forceinline__ void mma_bf16(float* d, const uint32_t* a, const uint32_t* b) {
    asm volatile(
        "mma.sync.aligned.m16n8k16.row.col.f32.bf16.bf16.f32 "
        "{%0,%1,%2,%3}, {%4,%5,%6,%7}, {%8,%9}, {%0,%1,%2,%3};"
        : "+f"(d[0]), "+f"(d[1]), "+f"(d[2]), "+f"(d[3])
        : "r"(a[0]), "r"(a[1]), "r"(a[2]), "r"(a[3]), "r"(b[0]), "r"(b[1]));
}
__device__ __forceinline__ void split2(float va, float vb, uint32_t& hi, uint32_t& lo) {
    __nv_bfloat16 ha = __float2bfloat16_rn(va);
    __nv_bfloat16 hb = __float2bfloat16_rn(vb);
    float ra = va - __bfloat162float(ha);
    float rb = vb - __bfloat162float(hb);
    __nv_bfloat162 hp; hp.x = ha; hp.y = hb;
    __nv_bfloat162 lp; lp.x = __float2bfloat16_rn(ra); lp.y = __float2bfloat16_rn(rb);
    hi = *(uint32_t*)&hp;
    lo = *(uint32_t*)&lp;
}
__device__ __forceinline__ float sigm(float x) { return 1.0f / (1.0f + __expf(-x)); }

// bar1: group-local (8 k-slice CTAs of one m-tile). thread0-only fence (R3 idiom).
__device__ __forceinline__ void group_barrier(volatile unsigned* c, unsigned target) {
    __syncthreads();
    if (threadIdx.x == 0) {
        __threadfence();                       // release partial stores
        atomicAdd((unsigned*)c, 1u);
        while (*c < target) { }
        __threadfence();                       // acquire
    }
    __syncthreads();
}

// bar2: hierarchical global. 8 REDs/group -> leader forwards 1 RED to g_bar (16 total).
__device__ __forceinline__ void grid_barrier(volatile unsigned* c, int leader,
                                             unsigned gtarget, unsigned target) {
    __syncthreads();
    if (threadIdx.x == 0) {
        __threadfence();                       // release h stores
        atomicAdd((unsigned*)c, 1u);
        if (leader) {
            while (*c < gtarget) { }
            __threadfence();
            atomicAdd(&g_bar, 1u);
        }
        while (*((volatile unsigned*)&g_bar) < target) __nanosleep(16);
        __threadfence();                       // acquire
    }
    __syncthreads();
}

// ---------------------------------------------------------------------------
// init: split x to bf16 hi/lo, zero h buffers, reset counters
__global__ void init_kernel(const float* __restrict__ x) {
    size_t i = (size_t)blockIdx.x * blockDim.x + threadIdx.x;
    if (i < (size_t)SEQ * BATCH * INPUT / 4) {
        float4 v = ((const float4*)x)[i];
        uint32_t h0, l0, h1, l1;
        split2(v.x, v.y, h0, l0);
        split2(v.z, v.w, h1, l1);
        ((uint2*)g_xhi)[i] = make_uint2(h0, h1);
        ((uint2*)g_xlo)[i] = make_uint2(l0, l1);
    }
    if (i < (size_t)2 * BATCH * HID / 4) {      // uint2 = 4 bf16
        ((uint2*)g_hhi)[i] = make_uint2(0u, 0u);
        ((uint2*)g_hlo)[i] = make_uint2(0u, 0u);
    }
    if (i < NM * 64) g_grp[i] = 0u;
    if (i == 0) g_bar = 0u;
}

// ---------------------------------------------------------------------------
__global__ __launch_bounds__(NTHR, 1)
void lstm_mma(Params P) {
    extern __shared__ char smem[];
    const uint32_t sb = smem_u32(smem);

    const int tid  = threadIdx.x;
    const int w    = tid >> 5;
    const int l    = tid & 31;
    const int mcta = blockIdx.x >> 3;   // 0..15
    const int ks   = blockIdx.x & 7;    // 0..7
    const int j0   = mcta * 64;
    volatile unsigned* grpc = &g_grp[mcta * 64];
    const int leader = (ks == 0);

    // ---- stage weights into smem (hi/lo bf16), once per launch ----
    {
        const int r = tid;
        const int gate = r >> 6, jl = r & 63, j = j0 + jl;
        const float4* wh = (const float4*)(P.Wh[gate] + (size_t)j * HID + ks * 128);
        const float4* wx = (const float4*)(P.Wx[gate] + (size_t)j * INPUT + ks * 32);
        char* ahi = smem + OFF_AHI + r * ASTR;
        char* alo = smem + OFF_ALO + r * ASTR;
        #pragma unroll 4
        for (int f = 0; f < 40; f++) {
            float4 v = (f < 32) ? wh[f] : wx[f - 32];
            uint32_t h0, l0, h1, l1;
            split2(v.x, v.y, h0, l0);
            split2(v.z, v.w, h1, l1);
            *(uint2*)(ahi + f * 8) = make_uint2(h0, h1);
            *(uint2*)(alo + f * 8) = make_uint2(l0, l1);
        }
    }

    // ---- ldmatrix lane addresses ----
    const uint32_t a_row = (uint32_t)(w * 32 + (l & 7) + ((l >> 3) & 1) * 8);
    const uint32_t a_colb = (uint32_t)(((l >> 4) & 1) * 16);
    const uint32_t aAddrHi0 = sb + OFF_AHI + a_row * ASTR + a_colb;
    const uint32_t aAddrHi1 = aAddrHi0 + 16 * ASTR;
    const uint32_t aAddrLo0 = aAddrHi0 + (OFF_ALO - OFF_AHI);
    const uint32_t aAddrLo1 = aAddrLo0 + 16 * ASTR;
    const uint32_t b_rowb = (uint32_t)((l & 7) * ASTR);
    const uint32_t b_colb = (uint32_t)(((l >> 3) & 1) * 16);
    const uint32_t bAddrHi = sb + OFF_BHI + b_rowb + b_colb;
    const uint32_t bAddrLo = bAddrHi + (OFF_BLO - OFF_BHI);

    // ---- pointwise cell ownership: 2 cells per thread ----
    const int pb  = ks * 8 + (tid & 7);
    const int jlA = tid >> 3;
    const int jlB = jlA + 32;
    const int jA  = j0 + jlA, jB = j0 + jlB;
    float biasA[4], biasB[4];
    #pragma unroll
    for (int g = 0; g < 4; g++) {
        biasA[g] = P.bh[g][jA] + P.bx[g][jA];
        biasB[g] = P.bh[g][jB] + P.bx[g][jB];
    }
    float cA = 0.0f, cB = 0.0f;

    float* out = P.out;
    const size_t BH  = (size_t)BATCH * HID;
    const size_t SBH = (size_t)SEQ * BH;

    // staging index precompute
    const int stb = tid >> 2;           // batch 0..63
    const int stf = tid & 3;            // phase 0..3
    const size_t hoff = (size_t)stb * HID + ks * 128;
    char* bhi_row = smem + OFF_BHI + stb * ASTR;
    char* blo_row = smem + OFF_BLO + stb * ASTR;
    const size_t x_row_off = (size_t)stb * INPUT + ks * 32;

    float* ppart = g_part + (size_t)(ks * NM + mcta) * RPC * BATCH;

    // ---- pre-loop: stage x(0) and h(0) (buffer 0, zeros) ----
    {
        const uint4* xs = (const uint4*)(g_xhi + x_row_off);
        const uint4* xl = (const uint4*)(g_xlo + x_row_off);
        *(uint4*)(bhi_row + 256 + stf * 16) = __ldcg(xs + stf);
        *(uint4*)(blo_row + 256 + stf * 16) = __ldcg(xl + stf);
        const uint4* hhi_src = (const uint4*)(g_hhi + hoff);
        const uint4* hlo_src = (const uint4*)(g_hlo + hoff);
        #pragma unroll
        for (int q = 0; q < 4; q++) {
            int idx = stf + q * 4;
            *(uint4*)(bhi_row + idx * 16) = __ldcg(hhi_src + idx);
            *(uint4*)(blo_row + idx * 16) = __ldcg(hlo_src + idx);
        }
    }
    __syncthreads();

    for (int t = 0; t < SEQ; t++) {
        // ---- GEMM: D[256 rows][64 b], 3-pass split bf16 ----
        float d[2][8][4];
        #pragma unroll
        for (int mt = 0; mt < 2; mt++)
            #pragma unroll
            for (int nt = 0; nt < 8; nt++)
                #pragma unroll
                for (int q = 0; q < 4; q++) d[mt][nt][q] = 0.0f;

        for (int kt = 0; kt < 10; kt++) {
            const uint32_t kb = (uint32_t)(kt * 32);
            uint32_t Ah0[4], Ah1[4], Al0[4], Al1[4];
            ldsm4(Ah0, aAddrHi0 + kb);
            ldsm4(Ah1, aAddrHi1 + kb);
            ldsm4(Al0, aAddrLo0 + kb);
            ldsm4(Al1, aAddrLo1 + kb);
            #pragma unroll
            for (int nt = 0; nt < 8; nt++) {
                uint32_t Bh[2], Bl[2];
                const uint32_t bo = (uint32_t)(nt * 8 * ASTR) + kb;
                ldsm2(Bh, bAddrHi + bo);
                ldsm2(Bl, bAddrLo + bo);
                mma_bf16(d[0][nt], Ah0, Bh);
                mma_bf16(d[1][nt], Ah1, Bh);
                mma_bf16(d[0][nt], Ah0, Bl);
                mma_bf16(d[1][nt], Ah1, Bl);
                mma_bf16(d[0][nt], Al0, Bh);
                mma_bf16(d[1][nt], Al1, Bh);
            }
        }

        // ---- store partials [row][b] ----
        {
            const int r0 = w * 32 + (l >> 2);
            const int c0 = (l & 3) * 2;
            #pragma unroll
            for (int mt = 0; mt < 2; mt++) {
                #pragma unroll
                for (int nt = 0; nt < 8; nt++) {
                    int row = r0 + mt * 16;
                    int col = nt * 8 + c0;
                    *(float2*)(ppart + (size_t)row * BATCH + col) =
                        make_float2(d[mt][nt][0], d[mt][nt][1]);
                    *(float2*)(ppart + (size_t)(row + 8) * BATCH + col) =
                        make_float2(d[mt][nt][2], d[mt][nt][3]);
                }
            }
        }

        // ---- B smem GEMM reads done -> stage x(t+1) (overlaps bar1) ----
        __syncthreads();
        if (t + 1 < SEQ) {
            const size_t xo = (size_t)(t + 1) * BATCH * INPUT + x_row_off;
            const uint4* xs = (const uint4*)(g_xhi + xo);
            const uint4* xl = (const uint4*)(g_xlo + xo);
            *(uint4*)(bhi_row + 256 + stf * 16) = __ldcg(xs + stf);
            *(uint4*)(blo_row + 256 + stf * 16) = __ldcg(xl + stf);
        }

        // ---- bar1: group-local; group counter epoch (2t+1)*8 ----
        group_barrier(grpc, (unsigned)(2 * t + 1) * NKS);

        // ---- reduce 8 k-slices + pointwise; h -> buf[(t+1)&1] ----
        {
            const size_t hw = (size_t)((t + 1) & 1) * BH;
            float accA[4], accB[4];
            #pragma unroll
            for (int g = 0; g < 4; g++) { accA[g] = biasA[g]; accB[g] = biasB[g]; }
            #pragma unroll
            for (int g = 0; g < 4; g++) {
                #pragma unroll
                for (int s = 0; s < NKS; s++) {
                    const float* pp = g_part + (size_t)(s * NM + mcta) * RPC * BATCH + pb;
                    accA[g] += __ldcg(pp + (size_t)(g * 64 + jlA) * BATCH);
                    accB[g] += __ldcg(pp + (size_t)(g * 64 + jlB) * BATCH);
                }
            }
            float f, i1, i2, o, hv;

            f = sigm(accA[0]); i1 = sigm(accA[1]); i2 = tanhf(accA[2]); o = sigm(accA[3]);
            cA = cA * f + i1 * i2;
            hv = tanhf(cA) * o;
            out[(size_t)t * BH + (size_t)pb * HID + jA] = hv;
            {
                __nv_bfloat16 hb = __float2bfloat16_rn(hv);
                g_hhi[hw + (size_t)pb * HID + jA] = hb;
                g_hlo[hw + (size_t)pb * HID + jA] = __float2bfloat16_rn(hv - __bfloat162float(hb));
            }
            if (t == SEQ - 1) {
                out[SBH + (size_t)pb * HID + jA] = hv;
                out[SBH + BH + (size_t)pb * HID + jA] = cA;
            }

            f = sigm(accB[0]); i1 = sigm(accB[1]); i2 = tanhf(accB[2]); o = sigm(accB[3]);
            cB = cB * f + i1 * i2;
            hv = tanhf(cB) * o;
            out[(size_t)t * BH + (size_t)pb * HID + jB] = hv;
            {
                __nv_bfloat16 hb = __float2bfloat16_rn(hv);
                g_hhi[hw + (size_t)pb * HID + jB] = hb;
                g_hlo[hw + (size_t)pb * HID + jB] = __float2bfloat16_rn(hv - __bfloat162float(hb));
            }
            if (t == SEQ - 1) {
                out[SBH + (size_t)pb * HID + jB] = hv;
                out[SBH + BH + (size_t)pb * HID + jB] = cB;
            }
        }

        // ---- bar2: hierarchical global; group epoch (2t+2)*8, global (t+1)*16 ----
        grid_barrier(grpc, leader, (unsigned)(2 * t + 2) * NKS, (unsigned)(t + 1) * NM);

        // ---- stage h(t+1) from buf[(t+1)&1] ----
        if (t + 1 < SEQ) {
            const size_t hr = (size_t)((t + 1) & 1) * BH + hoff;
            const uint4* hhi_src = (const uint4*)(g_hhi + hr);
            const uint4* hlo_src = (const uint4*)(g_hlo + hr);
            #pragma unroll
            for (int q = 0; q < 4; q++) {
                int idx = stf + q * 4;
                *(uint4*)(bhi_row + idx * 16) = __ldcg(hhi_src + idx);
                *(uint4*)(blo_row + idx * 16) = __ldcg(hlo_src + idx);
            }
            __syncthreads();
        }
    }
}

// ---------------------------------------------------------------------------
extern "C" void kernel_launch(void* const* d_in, const int* in_sizes, int n_in,
                              void* d_out, int out_size) {
    Params P;
    P.x = (const float*)d_in[0];
    P.Wx[0] = (const float*)d_in[1];  P.bx[0] = (const float*)d_in[2];
    P.Wx[1] = (const float*)d_in[3];  P.bx[1] = (const float*)d_in[4];
    P.Wx[2] = (const float*)d_in[5];  P.bx[2] = (const float*)d_in[6];
    P.Wx[3] = (const float*)d_in[7];  P.bx[3] = (const float*)d_in[8];
    P.Wh[0] = (const float*)d_in[9];  P.bh[0] = (const float*)d_in[10];
    P.Wh[1] = (const float*)d_in[11]; P.bh[1] = (const float*)d_in[12];
    P.Wh[2] = (const float*)d_in[13]; P.bh[2] = (const float*)d_in[14];
    P.Wh[3] = (const float*)d_in[15]; P.bh[3] = (const float*)d_in[16];
    P.out   = (float*)d_out;

    static bool attr_set = false;
    if (!attr_set) {
        cudaFuncSetAttribute(lstm_mma, cudaFuncAttributeMaxDynamicSharedMemorySize,
                             SMEM_TOTAL);
        attr_set = true;
    }

    init_kernel<<<(SEQ * BATCH * INPUT / 4 + 255) / 256, 256>>>(P.x);
    lstm_mma<<<NCTA, NTHR, SMEM_TOTAL>>>(P);
}

// round 8
// speedup vs baseline: 1.4965x; 1.1151x over previous
#include <cuda_runtime.h>
#include <cuda_fp16.h>
#include <cstdint>
#include <math.h>

// ---------------- problem dims ----------------
#define SEQ   512
#define BATCH 64
#define INPUT 256
#define HID   1024

// ---------------- config ----------------
#define NCTA  128            // 32 m-groups x 4 k-slices
#define NTHR  256
#define NM    32             // m-groups (128 gate-rows each: 4 gates x 32 j)
#define NKS   4              // k slices (320 k each: 256 h + 64 x)
#define RPC   128            // gate-rows per CTA
#define KSL   320
#define ASTR  656            // smem row stride bytes (320*2 + 16 pad; 41*16, odd)
#define OFF_AHI 0
#define OFF_ALO (RPC*ASTR)                  // 83968
#define OFF_B   (2*RPC*ASTR)                // 167936
#define SMEM_TOTAL (2*RPC*ASTR + BATCH*ASTR) // 209920

// ---------------- scratch ----------------
__device__ __align__(16) __half g_hh[2 * BATCH * HID];            // h fp16, double buffer
__device__ __align__(16) __half g_xh[(size_t)SEQ * BATCH * INPUT]; // x fp16
__device__ float    g_part[NKS * NM * RPC * BATCH];   // [ks][mg][row][b]  (4 MB)
__device__ unsigned g_bar;                            // global counter (leaders only)
__device__ unsigned g_grp[NM * 64];                   // per-group counters, 256B apart

struct Params {
    const float* x;
    const float* Wx[4]; const float* bx[4];
    const float* Wh[4]; const float* bh[4];
    float* out;
};

// ---------------- helpers ----------------
__device__ __forceinline__ uint32_t smem_u32(const void* p) {
    uint32_t a;
    asm("{ .reg .u64 t; cvta.to.shared.u64 t, %1; cvt.u32.u64 %0, t; }" : "=r"(a) : "l"(p));
    return a;
}
__device__ __forceinline__ void ldsm4(uint32_t* r, uint32_t addr) {
    asm volatile("ldmatrix.sync.aligned.m8n8.x4.shared.b16 {%0,%1,%2,%3}, [%4];"
        : "=r"(r[0]), "=r"(r[1]), "=r"(r[2]), "=r"(r[3]) : "r"(addr));
}
__device__ __forceinline__ void ldsm2(uint32_t* r, uint32_t addr) {
    asm volatile("ldmatrix.sync.aligned.m8n8.x2.shared.b16 {%0,%1}, [%2];"
        : "=r"(r[0]), "=r"(r[1]) : "r"(addr));
}
__device__ __forceinline__ void mma_f16(float* d, const uint32_t* a, const uint32_t* b) {
    asm volatile(
        "mma.sync.aligned.m16n8k16.row.col.f32.f16.f16.f32 "
        "{%0,%1,%2,%3}, {%4,%5,%6,%7}, {%8,%9}, {%0,%1,%2,%3};"
        : "+f"(d[0]), "+f"(d[1]), "+f"(d[2]), "+f"(d[3])
        : "r"(a[0]), "r"(a[1]), "r"(a[2]), "r"(a[3]), "r"(b[0]), "r"(b[1]));
}
// split two floats into packed fp16 hi pair + fp16 lo pair
__device__ __forceinline__ void split2h(float va, float vb, uint32_t& hi, uint32_t& lo) {
    __half ha = __float2half_rn(va);
    __half hb = __float2half_rn(vb);
    float ra = va - __half2float(ha);
    float rb = vb - __half2float(hb);
    __half2 hp = __halves2half2(ha, hb);
    __half2 lp = __halves2half2(__float2half_rn(ra), __float2half_rn(rb));
    hi = *(uint32_t*)&hp;
    lo = *(uint32_t*)&lp;
}
__device__ __forceinline__ float sigm(float x) { return 1.0f / (1.0f + __expf(-x)); }

// bar1: group-local (4 k-slice CTAs of one m-group); thread0 fence; throttled poll
__device__ __forceinline__ void group_barrier(volatile unsigned* c, unsigned target) {
    __syncthreads();
    if (threadIdx.x == 0) {
        __threadfence();
        atomicAdd((unsigned*)c, 1u);
        while (*c < target) __nanosleep(8);
        __threadfence();
    }
    __syncthreads();
}

// bar2: hierarchical global. 4 REDs/group -> ks==0 leader forwards 1 RED to g_bar.
__device__ __forceinline__ void grid_barrier(volatile unsigned* c, int leader,
                                             unsigned gtarget, unsigned target) {
    __syncthreads();
    if (threadIdx.x == 0) {
        __threadfence();
        atomicAdd((unsigned*)c, 1u);
        if (leader) {
            while (*c < gtarget) __nanosleep(8);
            __threadfence();
            atomicAdd(&g_bar, 1u);
        }
        while (*((volatile unsigned*)&g_bar) < target) __nanosleep(16);
        __threadfence();
    }
    __syncthreads();
}

// ---------------------------------------------------------------------------
// init: x -> fp16, zero h buffers, reset counters
__global__ void init_kernel(const float* __restrict__ x) {
    size_t i = (size_t)blockIdx.x * blockDim.x + threadIdx.x;
    if (i < (size_t)SEQ * BATCH * INPUT / 4) {
        float4 v = ((const float4*)x)[i];
        __half2 p0 = __halves2half2(__float2half_rn(v.x), __float2half_rn(v.y));
        __half2 p1 = __halves2half2(__float2half_rn(v.z), __float2half_rn(v.w));
        ((uint2*)g_xh)[i] = make_uint2(*(uint32_t*)&p0, *(uint32_t*)&p1);
    }
    if (i < (size_t)2 * BATCH * HID / 4) {       // uint2 = 4 fp16
        ((uint2*)g_hh)[i] = make_uint2(0u, 0u);
    }
    if (i < NM * 64) g_grp[i] = 0u;
    if (i == 0) g_bar = 0u;
}

// ---------------------------------------------------------------------------
__global__ __launch_bounds__(NTHR, 1)
void lstm_mma(Params P) {
    extern __shared__ char smem[];
    const uint32_t sb = smem_u32(smem);

    const int tid  = threadIdx.x;
    const int w    = tid >> 5;
    const int l    = tid & 31;
    const int mg   = blockIdx.x >> 2;   // 0..31
    const int ks   = blockIdx.x & 3;    // 0..3
    const int j0   = mg * 32;
    volatile unsigned* grpc = &g_grp[mg * 64];
    const int leader = (ks == 0);

    // ---- stage weights into smem (fp16 hi/lo), once per launch ----
    // 128 rows x 320 k; 2 threads per row, 160 k each
    {
        const int r    = tid >> 1;           // 0..127
        const int half = tid & 1;
        const int gate = r >> 5, jl = r & 31, j = j0 + jl;
        const float* whp = P.Wh[gate] + (size_t)j * HID + ks * 256;
        const float* wxp = P.Wx[gate] + (size_t)j * INPUT + ks * 64;
        char* ahi = smem + OFF_AHI + r * ASTR;
        char* alo = smem + OFF_ALO + r * ASTR;
        #pragma unroll 4
        for (int fi = 0; fi < 40; fi++) {
            int k = (half * 40 + fi) * 4;     // 0..316
            float4 v = (k < 256) ? *(const float4*)(whp + k)
                                 : *(const float4*)(wxp + (k - 256));
            uint32_t h0, l0, h1, l1;
            split2h(v.x, v.y, h0, l0);
            split2h(v.z, v.w, h1, l1);
            *(uint2*)(ahi + k * 2) = make_uint2(h0, h1);
            *(uint2*)(alo + k * 2) = make_uint2(l0, l1);
        }
    }

    // ---- ldmatrix lane addresses ----
    // A: warp w owns rows w*16..w*16+15 (one m16 tile)
    const uint32_t a_row  = (uint32_t)(w * 16 + (l & 15));
    const uint32_t a_colb = (uint32_t)((l >> 4) * 16);
    const uint32_t aAddrHi = sb + OFF_AHI + a_row * ASTR + a_colb;
    const uint32_t aAddrLo = aAddrHi + (OFF_ALO - OFF_AHI);
    const uint32_t b_rowb  = (uint32_t)((l & 7) * ASTR);
    const uint32_t b_colb  = (uint32_t)(((l >> 3) & 1) * 16);
    const uint32_t bAddr   = sb + OFF_B + b_rowb + b_colb;

    // ---- pointwise cell ownership: 2 cells per thread ----
    const int pb  = ks * 16 + (tid & 15);    // batch
    const int jlA = tid >> 4;                // 0..15
    const int jlB = jlA + 16;
    const int jA  = j0 + jlA, jB = j0 + jlB;
    float biasA[4], biasB[4];
    #pragma unroll
    for (int g = 0; g < 4; g++) {
        biasA[g] = P.bh[g][jA] + P.bx[g][jA];
        biasB[g] = P.bh[g][jB] + P.bx[g][jB];
    }
    float cA = 0.0f, cB = 0.0f;

    float* out = P.out;
    const size_t BH  = (size_t)BATCH * HID;
    const size_t SBH = (size_t)SEQ * BH;

    // staging map: thread -> (batch stb, segment stf); h: 128B/thread, x: 32B/thread
    const int stb = tid >> 2;           // 0..63
    const int stf = tid & 3;            // 0..3
    const size_t hoff = (size_t)stb * HID + ks * 256 + stf * 64;   // 64 fp16 = 128B
    char* b_row = smem + OFF_B + stb * ASTR;
    const size_t x_off = (size_t)stb * INPUT + ks * 64 + stf * 16; // 16 fp16 = 32B

    float* ppart = g_part + (size_t)(ks * NM + mg) * RPC * BATCH;

    // ---- pre-loop: stage x(0) and h(0) (buffer 0 = zeros) ----
    {
        const uint4* xs = (const uint4*)(g_xh + x_off);
        *(uint4*)(b_row + 512 + stf * 32)      = __ldcg(xs + 0);
        *(uint4*)(b_row + 512 + stf * 32 + 16) = __ldcg(xs + 1);
        const uint4* hs = (const uint4*)(g_hh + hoff);
        #pragma unroll
        for (int q = 0; q < 8; q++)
            *(uint4*)(b_row + stf * 128 + q * 16) = __ldcg(hs + q);
    }
    __syncthreads();

    for (int t = 0; t < SEQ; t++) {
        // ---- GEMM: D[128 rows][64 b] = (Ahi+Alo) * B, 2-pass fp16 ----
        float d[8][4];
        #pragma unroll
        for (int nt = 0; nt < 8; nt++)
            #pragma unroll
            for (int q = 0; q < 4; q++) d[nt][q] = 0.0f;

        for (int kt = 0; kt < 20; kt++) {
            const uint32_t kb = (uint32_t)(kt * 32);
            uint32_t Ah[4], Al[4];
            ldsm4(Ah, aAddrHi + kb);
            ldsm4(Al, aAddrLo + kb);
            #pragma unroll
            for (int nt = 0; nt < 8; nt++) {
                uint32_t B2[2];
                ldsm2(B2, bAddr + (uint32_t)(nt * 8 * ASTR) + kb);
                mma_f16(d[nt], Ah, B2);
                mma_f16(d[nt], Al, B2);
            }
        }

        // ---- store partials [row][b] ----
        {
            const int r0 = w * 16 + (l >> 2);
            const int c0 = (l & 3) * 2;
            #pragma unroll
            for (int nt = 0; nt < 8; nt++) {
                int col = nt * 8 + c0;
                *(float2*)(ppart + (size_t)r0 * BATCH + col) =
                    make_float2(d[nt][0], d[nt][1]);
                *(float2*)(ppart + (size_t)(r0 + 8) * BATCH + col) =
                    make_float2(d[nt][2], d[nt][3]);
            }
        }

        // ---- B smem reads done -> stage x(t+1) (overlaps bar1) ----
        __syncthreads();
        if (t + 1 < SEQ) {
            const uint4* xs = (const uint4*)(g_xh + (size_t)(t + 1) * BATCH * INPUT + x_off);
            *(uint4*)(b_row + 512 + stf * 32)      = __ldcg(xs + 0);
            *(uint4*)(b_row + 512 + stf * 32 + 16) = __ldcg(xs + 1);
        }

        // ---- bar1: group-local (4 CTAs); epoch (2t+1)*4 ----
        group_barrier(grpc, (unsigned)(2 * t + 1) * NKS);

        // ---- reduce 4 k-slices + pointwise (2 cells); h -> buf[(t+1)&1] ----
        {
            const size_t hw = (size_t)((t + 1) & 1) * BH;
            float accA[4], accB[4];
            #pragma unroll
            for (int g = 0; g < 4; g++) { accA[g] = biasA[g]; accB[g] = biasB[g]; }
            #pragma unroll
            for (int g = 0; g < 4; g++) {
                #pragma unroll
                for (int s = 0; s < NKS; s++) {
                    const float* pp = g_part + (size_t)(s * NM + mg) * RPC * BATCH + pb;
                    accA[g] += __ldcg(pp + (size_t)(g * 32 + jlA) * BATCH);
                    accB[g] += __ldcg(pp + (size_t)(g * 32 + jlB) * BATCH);
                }
            }
            float f, i1, i2, o, hv;

            f = sigm(accA[0]); i1 = sigm(accA[1]); i2 = tanhf(accA[2]); o = sigm(accA[3]);
            cA = cA * f + i1 * i2;
            hv = tanhf(cA) * o;
            out[(size_t)t * BH + (size_t)pb * HID + jA] = hv;
            g_hh[hw + (size_t)pb * HID + jA] = __float2half_rn(hv);
            if (t == SEQ - 1) {
                out[SBH + (size_t)pb * HID + jA] = hv;
                out[SBH + BH + (size_t)pb * HID + jA] = cA;
            }

            f = sigm(accB[0]); i1 = sigm(accB[1]); i2 = tanhf(accB[2]); o = sigm(accB[3]);
            cB = cB * f + i1 * i2;
            hv = tanhf(cB) * o;
            out[(size_t)t * BH + (size_t)pb * HID + jB] = hv;
            g_hh[hw + (size_t)pb * HID + jB] = __float2half_rn(hv);
            if (t == SEQ - 1) {
                out[SBH + (size_t)pb * HID + jB] = hv;
                out[SBH + BH + (size_t)pb * HID + jB] = cB;
            }
        }

        // ---- bar2: hierarchical global; group epoch (2t+2)*4, global (t+1)*32 ----
        grid_barrier(grpc, leader, (unsigned)(2 * t + 2) * NKS, (unsigned)(t + 1) * NM);

        // ---- stage h(t+1) from buf[(t+1)&1] ----
        if (t + 1 < SEQ) {
            const uint4* hs = (const uint4*)(g_hh + (size_t)((t + 1) & 1) * BH + hoff);
            #pragma unroll
            for (int q = 0; q < 8; q++)
                *(uint4*)(b_row + stf * 128 + q * 16) = __ldcg(hs + q);
            __syncthreads();
        }
    }
}

// ---------------------------------------------------------------------------
extern "C" void kernel_launch(void* const* d_in, const int* in_sizes, int n_in,
                              void* d_out, int out_size) {
    Params P;
    P.x = (const float*)d_in[0];
    P.Wx[0] = (const float*)d_in[1];  P.bx[0] = (const float*)d_in[2];
    P.Wx[1] = (const float*)d_in[3];  P.bx[1] = (const float*)d_in[4];
    P.Wx[2] = (const float*)d_in[5];  P.bx[2] = (const float*)d_in[6];
    P.Wx[3] = (const float*)d_in[7];  P.bx[3] = (const float*)d_in[8];
    P.Wh[0] = (const float*)d_in[9];  P.bh[0] = (const float*)d_in[10];
    P.Wh[1] = (const float*)d_in[11]; P.bh[1] = (const float*)d_in[12];
    P.Wh[2] = (const float*)d_in[13]; P.bh[2] = (const float*)d_in[14];
    P.Wh[3] = (const float*)d_in[15]; P.bh[3] = (const float*)d_in[16];
    P.out   = (float*)d_out;

    static bool attr_set = false;
    if (!attr_set) {
        cudaFuncSetAttribute(lstm_mma, cudaFuncAttributeMaxDynamicSharedMemorySize,
                             SMEM_TOTAL);
        attr_set = true;
    }

    init_kernel<<<(SEQ * BATCH * INPUT / 4 + 255) / 256, 256>>>(P.x);
    lstm_mma<<<NCTA, NTHR, SMEM_TOTAL>>>(P);
}

// round 9
// speedup vs baseline: 2.0018x; 1.3377x over previous
#include <cuda_runtime.h>
#include <cuda_fp16.h>
#include <cstdint>
#include <math.h>

// ---------------- problem dims ----------------
#define SEQ   512
#define BATCH 64
#define INPUT 256
#define HID   1024

// ---------------- config ----------------
#define NCTA  128            // 32 m-groups x 4 k-slices
#define NTHR  256
#define NM    32             // m-groups (128 gate-rows each: 4 gates x 32 j)
#define NKS   4              // k slices (320 k each: 256 h + 64 x)
#define RPC   128            // gate-rows per CTA
#define ASTR  656            // smem row stride bytes (320*2 + 16 pad)
#define OFF_A 0
#define OFF_B (RPC*ASTR)                    // 83968
#define SMEM_TOTAL (RPC*ASTR + BATCH*ASTR)  // 125952

// ---------------- scratch ----------------
__device__ __align__(16) __half g_hh[2 * BATCH * HID];             // h fp16, double buffer
__device__ __align__(16) __half g_xh[(size_t)SEQ * BATCH * INPUT]; // x fp16
__device__ float    g_part[NKS * NM * RPC * BATCH];   // [ks][mg][row][b]  (4 MB)
__device__ unsigned g_bar;                            // global counter
__device__ unsigned g_grp[NM * 64];                   // per-group counters, 256B apart

struct Params {
    const float* x;
    const float* Wx[4]; const float* bx[4];
    const float* Wh[4]; const float* bh[4];
    float* out;
};

// ---------------- helpers ----------------
__device__ __forceinline__ uint32_t smem_u32(const void* p) {
    uint32_t a;
    asm("{ .reg .u64 t; cvta.to.shared.u64 t, %1; cvt.u32.u64 %0, t; }" : "=r"(a) : "l"(p));
    return a;
}
__device__ __forceinline__ void ldsm4(uint32_t* r, uint32_t addr) {
    asm volatile("ldmatrix.sync.aligned.m8n8.x4.shared.b16 {%0,%1,%2,%3}, [%4];"
        : "=r"(r[0]), "=r"(r[1]), "=r"(r[2]), "=r"(r[3]) : "r"(addr));
}
__device__ __forceinline__ void ldsm2(uint32_t* r, uint32_t addr) {
    asm volatile("ldmatrix.sync.aligned.m8n8.x2.shared.b16 {%0,%1}, [%2];"
        : "=r"(r[0]), "=r"(r[1]) : "r"(addr));
}
__device__ __forceinline__ void mma_f16(float* d, const uint32_t* a, const uint32_t* b) {
    asm volatile(
        "mma.sync.aligned.m16n8k16.row.col.f32.f16.f16.f32 "
        "{%0,%1,%2,%3}, {%4,%5,%6,%7}, {%8,%9}, {%0,%1,%2,%3};"
        : "+f"(d[0]), "+f"(d[1]), "+f"(d[2]), "+f"(d[3])
        : "r"(a[0]), "r"(a[1]), "r"(a[2]), "r"(a[3]), "r"(b[0]), "r"(b[1]));
}
__device__ __forceinline__ uint32_t pack2h(float va, float vb) {
    __half2 p = __halves2half2(__float2half_rn(va), __float2half_rn(vb));
    return *(uint32_t*)&p;
}
__device__ __forceinline__ float sigm(float x) { return 1.0f / (1.0f + __expf(-x)); }

// bar1: group-local (4 k-slice CTAs of one m-group)
__device__ __forceinline__ void group_barrier(volatile unsigned* c, unsigned target) {
    __syncthreads();
    if (threadIdx.x == 0) {
        __threadfence();
        atomicAdd((unsigned*)c, 1u);
        while (*c < target) __nanosleep(8);
        __threadfence();
    }
    __syncthreads();
}

// bar2: single-level global (R3-proven form)
__device__ __forceinline__ void grid_barrier(unsigned target) {
    __syncthreads();
    if (threadIdx.x == 0) {
        __threadfence();
        atomicAdd(&g_bar, 1u);
        while (*((volatile unsigned*)&g_bar) < target) __nanosleep(16);
        __threadfence();
    }
    __syncthreads();
}

// ---------------------------------------------------------------------------
// init: x -> fp16, zero h buffers, reset counters
__global__ void init_kernel(const float* __restrict__ x) {
    size_t i = (size_t)blockIdx.x * blockDim.x + threadIdx.x;
    if (i < (size_t)SEQ * BATCH * INPUT / 4) {
        float4 v = ((const float4*)x)[i];
        ((uint2*)g_xh)[i] = make_uint2(pack2h(v.x, v.y), pack2h(v.z, v.w));
    }
    if (i < (size_t)2 * BATCH * HID / 4) {
        ((uint2*)g_hh)[i] = make_uint2(0u, 0u);
    }
    if (i < NM * 64) g_grp[i] = 0u;
    if (i == 0) g_bar = 0u;
}

// ---------------------------------------------------------------------------
__global__ __launch_bounds__(NTHR, 1)
void lstm_mma(Params P) {
    extern __shared__ char smem[];
    const uint32_t sb = smem_u32(smem);

    const int tid  = threadIdx.x;
    const int w    = tid >> 5;
    const int l    = tid & 31;
    const int mg   = blockIdx.x >> 2;   // 0..31
    const int ks   = blockIdx.x & 3;    // 0..3
    const int j0   = mg * 32;
    volatile unsigned* grpc = &g_grp[mg * 64];

    // ---- stage weights into smem (single fp16), once per launch ----
    // 128 rows x 320 k; 2 threads per row, 160 k each
    {
        const int r    = tid >> 1;           // 0..127
        const int half = tid & 1;
        const int gate = r >> 5, jl = r & 31, j = j0 + jl;
        const float* whp = P.Wh[gate] + (size_t)j * HID + ks * 256;
        const float* wxp = P.Wx[gate] + (size_t)j * INPUT + ks * 64;
        char* arow = smem + OFF_A + r * ASTR;
        #pragma unroll 4
        for (int fi = 0; fi < 40; fi++) {
            int k = (half * 40 + fi) * 4;     // 0..316
            float4 v = (k < 256) ? *(const float4*)(whp + k)
                                 : *(const float4*)(wxp + (k - 256));
            *(uint2*)(arow + k * 2) = make_uint2(pack2h(v.x, v.y), pack2h(v.z, v.w));
        }
    }

    // ---- warp tile: 32 rows x 32 cols (wm = w&3 row-block, wn = w>>2 col-half) ----
    const int wm = w & 3;
    const int wn = w >> 2;
    const uint32_t a_row  = (uint32_t)(wm * 32 + (l & 15));
    const uint32_t a_colb = (uint32_t)((l >> 4) * 16);
    const uint32_t aAddr0 = sb + OFF_A + a_row * ASTR + a_colb;   // m-tile 0
    const uint32_t aAddr1 = aAddr0 + 16 * ASTR;                   // m-tile 1
    const uint32_t bAddr  = sb + OFF_B + (uint32_t)(wn * 32 + (l & 7)) * ASTR
                            + (uint32_t)(((l >> 3) & 1) * 16);

    // ---- pointwise cell ownership: 2 cells per thread ----
    const int pb  = ks * 16 + (tid & 15);    // batch
    const int jlA = tid >> 4;                // 0..15
    const int jlB = jlA + 16;
    const int jA  = j0 + jlA, jB = j0 + jlB;
    float biasA[4], biasB[4];
    #pragma unroll
    for (int g = 0; g < 4; g++) {
        biasA[g] = P.bh[g][jA] + P.bx[g][jA];
        biasB[g] = P.bh[g][jB] + P.bx[g][jB];
    }
    float cA = 0.0f, cB = 0.0f;

    float* out = P.out;
    const size_t BH  = (size_t)BATCH * HID;
    const size_t SBH = (size_t)SEQ * BH;

    // staging map: thread -> (batch stb, segment stf)
    const int stb = tid >> 2;           // 0..63
    const int stf = tid & 3;            // 0..3
    const size_t hoff = (size_t)stb * HID + ks * 256 + stf * 64;   // 64 fp16 = 128B
    char* b_row = smem + OFF_B + stb * ASTR;
    const size_t x_off = (size_t)stb * INPUT + ks * 64 + stf * 16; // 16 fp16 = 32B

    float* ppart = g_part + (size_t)(ks * NM + mg) * RPC * BATCH;

    // ---- pre-loop: stage x(0) and h(0) (buffer 0 = zeros) ----
    {
        const uint4* xs = (const uint4*)(g_xh + x_off);
        *(uint4*)(b_row + 512 + stf * 32)      = __ldcg(xs + 0);
        *(uint4*)(b_row + 512 + stf * 32 + 16) = __ldcg(xs + 1);
        const uint4* hs = (const uint4*)(g_hh + hoff);
        #pragma unroll
        for (int q = 0; q < 8; q++)
            *(uint4*)(b_row + stf * 128 + q * 16) = __ldcg(hs + q);
    }
    __syncthreads();

    for (int t = 0; t < SEQ; t++) {
        // ---- GEMM: D[128 rows][64 b] = A * B, single-pass fp16 ----
        float d[2][4][4];
        #pragma unroll
        for (int mt = 0; mt < 2; mt++)
            #pragma unroll
            for (int nt = 0; nt < 4; nt++)
                #pragma unroll
                for (int q = 0; q < 4; q++) d[mt][nt][q] = 0.0f;

        for (int kt = 0; kt < 20; kt++) {
            const uint32_t kb = (uint32_t)(kt * 32);
            uint32_t A0[4], A1[4];
            ldsm4(A0, aAddr0 + kb);
            ldsm4(A1, aAddr1 + kb);
            #pragma unroll
            for (int nt = 0; nt < 4; nt++) {
                uint32_t B2[2];
                ldsm2(B2, bAddr + (uint32_t)(nt * 8 * ASTR) + kb);
                mma_f16(d[0][nt], A0, B2);
                mma_f16(d[1][nt], A1, B2);
            }
        }

        // ---- store partials [row][b] ----
        {
            const int r0 = wm * 32 + (l >> 2);
            const int c0 = wn * 32 + (l & 3) * 2;
            #pragma unroll
            for (int mt = 0; mt < 2; mt++) {
                #pragma unroll
                for (int nt = 0; nt < 4; nt++) {
                    int row = r0 + mt * 16;
                    int col = c0 + nt * 8;
                    *(float2*)(ppart + (size_t)row * BATCH + col) =
                        make_float2(d[mt][nt][0], d[mt][nt][1]);
                    *(float2*)(ppart + (size_t)(row + 8) * BATCH + col) =
                        make_float2(d[mt][nt][2], d[mt][nt][3]);
                }
            }
        }

        // ---- B smem reads done -> stage x(t+1) (overlaps bar1) ----
        __syncthreads();
        if (t + 1 < SEQ) {
            const uint4* xs = (const uint4*)(g_xh + (size_t)(t + 1) * BATCH * INPUT + x_off);
            *(uint4*)(b_row + 512 + stf * 32)      = __ldcg(xs + 0);
            *(uint4*)(b_row + 512 + stf * 32 + 16) = __ldcg(xs + 1);
        }

        // ---- bar1: group-local (4 CTAs) ----
        group_barrier(grpc, (unsigned)(t + 1) * NKS);

        // ---- reduce 4 k-slices + pointwise (2 cells); h -> buf[(t+1)&1] ----
        {
            const size_t hw = (size_t)((t + 1) & 1) * BH;
            float accA[4], accB[4];
            #pragma unroll
            for (int g = 0; g < 4; g++) { accA[g] = biasA[g]; accB[g] = biasB[g]; }
            #pragma unroll
            for (int g = 0; g < 4; g++) {
                #pragma unroll
                for (int s = 0; s < NKS; s++) {
                    const float* pp = g_part + (size_t)(s * NM + mg) * RPC * BATCH + pb;
                    accA[g] += __ldcg(pp + (size_t)(g * 32 + jlA) * BATCH);
                    accB[g] += __ldcg(pp + (size_t)(g * 32 + jlB) * BATCH);
                }
            }
            float f, i1, i2, o, hv;

            f = sigm(accA[0]); i1 = sigm(accA[1]); i2 = tanhf(accA[2]); o = sigm(accA[3]);
            cA = cA * f + i1 * i2;
            hv = tanhf(cA) * o;
            out[(size_t)t * BH + (size_t)pb * HID + jA] = hv;
            g_hh[hw + (size_t)pb * HID + jA] = __float2half_rn(hv);
            if (t == SEQ - 1) {
                out[SBH + (size_t)pb * HID + jA] = hv;
                out[SBH + BH + (size_t)pb * HID + jA] = cA;
            }

            f = sigm(accB[0]); i1 = sigm(accB[1]); i2 = tanhf(accB[2]); o = sigm(accB[3]);
            cB = cB * f + i1 * i2;
            hv = tanhf(cB) * o;
            out[(size_t)t * BH + (size_t)pb * HID + jB] = hv;
            g_hh[hw + (size_t)pb * HID + jB] = __float2half_rn(hv);
            if (t == SEQ - 1) {
                out[SBH + (size_t)pb * HID + jB] = hv;
                out[SBH + BH + (size_t)pb * HID + jB] = cB;
            }
        }

        // ---- bar2: global (h visibility) ----
        grid_barrier((unsigned)(t + 1) * NCTA);

        // ---- stage h(t+1) from buf[(t+1)&1] ----
        if (t + 1 < SEQ) {
            const uint4* hs = (const uint4*)(g_hh + (size_t)((t + 1) & 1) * BH + hoff);
            #pragma unroll
            for (int q = 0; q < 8; q++)
                *(uint4*)(b_row + stf * 128 + q * 16) = __ldcg(hs + q);
            __syncthreads();
        }
    }
}

// ---------------------------------------------------------------------------
extern "C" void kernel_launch(void* const* d_in, const int* in_sizes, int n_in,
                              void* d_out, int out_size) {
    Params P;
    P.x = (const float*)d_in[0];
    P.Wx[0] = (const float*)d_in[1];  P.bx[0] = (const float*)d_in[2];
    P.Wx[1] = (const float*)d_in[3];  P.bx[1] = (const float*)d_in[4];
    P.Wx[2] = (const float*)d_in[5];  P.bx[2] = (const float*)d_in[6];
    P.Wx[3] = (const float*)d_in[7];  P.bx[3] = (const float*)d_in[8];
    P.Wh[0] = (const float*)d_in[9];  P.bh[0] = (const float*)d_in[10];
    P.Wh[1] = (const float*)d_in[11]; P.bh[1] = (const float*)d_in[12];
    P.Wh[2] = (const float*)d_in[13]; P.bh[2] = (const float*)d_in[14];
    P.Wh[3] = (const float*)d_in[15]; P.bh[3] = (const float*)d_in[16];
    P.out   = (float*)d_out;

    static bool attr_set = false;
    if (!attr_set) {
        cudaFuncSetAttribute(lstm_mma, cudaFuncAttributeMaxDynamicSharedMemorySize,
                             SMEM_TOTAL);
        attr_set = true;
    }

    init_kernel<<<(SEQ * BATCH * INPUT / 4 + 255) / 256, 256>>>(P.x);
    lstm_mma<<<NCTA, NTHR, SMEM_TOTAL>>>(P);
}

// round 10
// speedup vs baseline: 2.0029x; 1.0005x over previous
#include <cuda_runtime.h>
#include <cuda_fp16.h>
#include <cstdint>
#include <math.h>

// ---------------- problem dims ----------------
#define SEQ   512
#define BATCH 64
#define INPUT 256
#define HID   1024

// ---------------- config ----------------
#define NCTA  128            // 32 m-groups x 4 k-slices
#define NTHR  256
#define NM    32             // m-groups (128 gate-rows each: 4 gates x 32 j)
#define NKS   4              // k slices (320 k each: 256 h + 64 x)
#define RPC   128            // gate-rows per CTA
#define ASTR  656            // smem row stride bytes (320*2 + 16 pad)
#define OFF_A 0
#define OFF_B (RPC*ASTR)                    // 83968
#define SMEM_TOTAL (RPC*ASTR + BATCH*ASTR)  // 125952

// ---------------- scratch ----------------
__device__ __align__(16) __half g_hh[2 * BATCH * HID];             // h fp16, double buffer
__device__ __align__(16) __half g_xh[(size_t)SEQ * BATCH * INPUT]; // x fp16
__device__ float    g_part[NKS * NM * RPC * BATCH];   // [ks][mg][row][b]  (4 MB)
// per-group counter lines, 256B per group: +0 = bar1 (partials), +32 = ready (pointwise)
__device__ unsigned g_grp[NM * 64];

struct Params {
    const float* x;
    const float* Wx[4]; const float* bx[4];
    const float* Wh[4]; const float* bh[4];
    float* out;
};

// ---------------- helpers ----------------
__device__ __forceinline__ uint32_t smem_u32(const void* p) {
    uint32_t a;
    asm("{ .reg .u64 t; cvta.to.shared.u64 t, %1; cvt.u32.u64 %0, t; }" : "=r"(a) : "l"(p));
    return a;
}
__device__ __forceinline__ void ldsm4(uint32_t* r, uint32_t addr) {
    asm volatile("ldmatrix.sync.aligned.m8n8.x4.shared.b16 {%0,%1,%2,%3}, [%4];"
        : "=r"(r[0]), "=r"(r[1]), "=r"(r[2]), "=r"(r[3]) : "r"(addr));
}
__device__ __forceinline__ void ldsm2(uint32_t* r, uint32_t addr) {
    asm volatile("ldmatrix.sync.aligned.m8n8.x2.shared.b16 {%0,%1}, [%2];"
        : "=r"(r[0]), "=r"(r[1]) : "r"(addr));
}
__device__ __forceinline__ void mma_f16(float* d, const uint32_t* a, const uint32_t* b) {
    asm volatile(
        "mma.sync.aligned.m16n8k16.row.col.f32.f16.f16.f32 "
        "{%0,%1,%2,%3}, {%4,%5,%6,%7}, {%8,%9}, {%0,%1,%2,%3};"
        : "+f"(d[0]), "+f"(d[1]), "+f"(d[2]), "+f"(d[3])
        : "r"(a[0]), "r"(a[1]), "r"(a[2]), "r"(a[3]), "r"(b[0]), "r"(b[1]));
}
__device__ __forceinline__ uint32_t pack2h(float va, float vb) {
    __half2 p = __halves2half2(__float2half_rn(va), __float2half_rn(vb));
    return *(uint32_t*)&p;
}
__device__ __forceinline__ float sigm(float x) { return 1.0f / (1.0f + __expf(-x)); }

// bar1: group-local (4 k-slice CTAs of one m-group)
__device__ __forceinline__ void group_barrier(volatile unsigned* c, unsigned target) {
    __syncthreads();
    if (threadIdx.x == 0) {
        __threadfence();
        atomicAdd((unsigned*)c, 1u);
        while (*c < target) __nanosleep(8);
        __threadfence();
    }
    __syncthreads();
}

// ---------------------------------------------------------------------------
// init: x -> fp16, zero h buffers, reset counters
__global__ void init_kernel(const float* __restrict__ x) {
    size_t i = (size_t)blockIdx.x * blockDim.x + threadIdx.x;
    if (i < (size_t)SEQ * BATCH * INPUT / 4) {
        float4 v = ((const float4*)x)[i];
        ((uint2*)g_xh)[i] = make_uint2(pack2h(v.x, v.y), pack2h(v.z, v.w));
    }
    if (i < (size_t)2 * BATCH * HID / 4) {
        ((uint2*)g_hh)[i] = make_uint2(0u, 0u);
    }
    if (i < NM * 64) g_grp[i] = 0u;
}

// ---------------------------------------------------------------------------
__global__ __launch_bounds__(NTHR, 1)
void lstm_mma(Params P) {
    extern __shared__ char smem[];
    const uint32_t sb = smem_u32(smem);

    const int tid  = threadIdx.x;
    const int w    = tid >> 5;
    const int l    = tid & 31;
    const int mg   = blockIdx.x >> 2;   // 0..31
    const int ks   = blockIdx.x & 3;    // 0..3
    const int j0   = mg * 32;
    volatile unsigned* grpc  = &g_grp[mg * 64];        // bar1 line
    unsigned* readyc = (unsigned*)&g_grp[mg * 64 + 32]; // ready line (128B apart)

    // dep-poll line for threads 1..9: 8 dep groups + self
    volatile unsigned* depc = 0;
    if (tid >= 1 && tid <= 9) {
        int pt = tid - 1;
        int dg = (pt < 8) ? (ks * 8 + pt) : mg;
        depc = &g_grp[dg * 64 + 32];
    }

    // ---- stage weights into smem (single fp16), once per launch ----
    {
        const int r    = tid >> 1;           // 0..127
        const int half = tid & 1;
        const int gate = r >> 5, jl = r & 31, j = j0 + jl;
        const float* whp = P.Wh[gate] + (size_t)j * HID + ks * 256;
        const float* wxp = P.Wx[gate] + (size_t)j * INPUT + ks * 64;
        char* arow = smem + OFF_A + r * ASTR;
        #pragma unroll 4
        for (int fi = 0; fi < 40; fi++) {
            int k = (half * 40 + fi) * 4;     // 0..316
            float4 v = (k < 256) ? *(const float4*)(whp + k)
                                 : *(const float4*)(wxp + (k - 256));
            *(uint2*)(arow + k * 2) = make_uint2(pack2h(v.x, v.y), pack2h(v.z, v.w));
        }
    }

    // ---- warp tile: 32 rows x 32 cols ----
    const int wm = w & 3;
    const int wn = w >> 2;
    const uint32_t a_row  = (uint32_t)(wm * 32 + (l & 15));
    const uint32_t a_colb = (uint32_t)((l >> 4) * 16);
    const uint32_t aAddr0 = sb + OFF_A + a_row * ASTR + a_colb;
    const uint32_t aAddr1 = aAddr0 + 16 * ASTR;
    const uint32_t bAddr  = sb + OFF_B + (uint32_t)(wn * 32 + (l & 7)) * ASTR
                            + (uint32_t)(((l >> 3) & 1) * 16);

    // ---- pointwise cell ownership: 2 cells per thread ----
    const int pb  = ks * 16 + (tid & 15);    // batch
    const int jlA = tid >> 4;                // 0..15
    const int jlB = jlA + 16;
    const int jA  = j0 + jlA, jB = j0 + jlB;
    float biasA[4], biasB[4];
    #pragma unroll
    for (int g = 0; g < 4; g++) {
        biasA[g] = P.bh[g][jA] + P.bx[g][jA];
        biasB[g] = P.bh[g][jB] + P.bx[g][jB];
    }
    float cA = 0.0f, cB = 0.0f;

    float* out = P.out;
    const size_t BH  = (size_t)BATCH * HID;
    const size_t SBH = (size_t)SEQ * BH;

    // staging map
    const int stb = tid >> 2;           // 0..63
    const int stf = tid & 3;            // 0..3
    const size_t hoff = (size_t)stb * HID + ks * 256 + stf * 64;   // 64 fp16 = 128B
    char* b_row = smem + OFF_B + stb * ASTR;
    const size_t x_off = (size_t)stb * INPUT + ks * 64 + stf * 16;

    float* ppart = g_part + (size_t)(ks * NM + mg) * RPC * BATCH;

    // ---- pre-loop: stage x(0) and h(0) (buffer 0 = zeros) ----
    {
        const uint4* xs = (const uint4*)(g_xh + x_off);
        *(uint4*)(b_row + 512 + stf * 32)      = __ldcg(xs + 0);
        *(uint4*)(b_row + 512 + stf * 32 + 16) = __ldcg(xs + 1);
        const uint4* hs = (const uint4*)(g_hh + hoff);
        #pragma unroll
        for (int q = 0; q < 8; q++)
            *(uint4*)(b_row + stf * 128 + q * 16) = __ldcg(hs + q);
    }
    __syncthreads();

    for (int t = 0; t < SEQ; t++) {
        // ---- GEMM: D[128 rows][64 b] = A * B, single-pass fp16 ----
        float d[2][4][4];
        #pragma unroll
        for (int mt = 0; mt < 2; mt++)
            #pragma unroll
            for (int nt = 0; nt < 4; nt++)
                #pragma unroll
                for (int q = 0; q < 4; q++) d[mt][nt][q] = 0.0f;

        for (int kt = 0; kt < 20; kt++) {
            const uint32_t kb = (uint32_t)(kt * 32);
            uint32_t A0[4], A1[4];
            ldsm4(A0, aAddr0 + kb);
            ldsm4(A1, aAddr1 + kb);
            #pragma unroll
            for (int nt = 0; nt < 4; nt++) {
                uint32_t B2[2];
                ldsm2(B2, bAddr + (uint32_t)(nt * 8 * ASTR) + kb);
                mma_f16(d[0][nt], A0, B2);
                mma_f16(d[1][nt], A1, B2);
            }
        }

        // ---- store partials [row][b] ----
        {
            const int r0 = wm * 32 + (l >> 2);
            const int c0 = wn * 32 + (l & 3) * 2;
            #pragma unroll
            for (int mt = 0; mt < 2; mt++) {
                #pragma unroll
                for (int nt = 0; nt < 4; nt++) {
                    int row = r0 + mt * 16;
                    int col = c0 + nt * 8;
                    *(float2*)(ppart + (size_t)row * BATCH + col) =
                        make_float2(d[mt][nt][0], d[mt][nt][1]);
                    *(float2*)(ppart + (size_t)(row + 8) * BATCH + col) =
                        make_float2(d[mt][nt][2], d[mt][nt][3]);
                }
            }
        }

        // ---- B smem reads done -> stage x(t+1) (overlaps bar1) ----
        __syncthreads();
        if (t + 1 < SEQ) {
            const uint4* xs = (const uint4*)(g_xh + (size_t)(t + 1) * BATCH * INPUT + x_off);
            *(uint4*)(b_row + 512 + stf * 32)      = __ldcg(xs + 0);
            *(uint4*)(b_row + 512 + stf * 32 + 16) = __ldcg(xs + 1);
        }

        // ---- bar1: group-local (4 CTAs) ----
        group_barrier(grpc, (unsigned)(t + 1) * NKS);

        // ---- reduce 4 k-slices + pointwise (2 cells); h -> buf[(t+1)&1] ----
        {
            const size_t hw = (size_t)((t + 1) & 1) * BH;
            float accA[4], accB[4];
            #pragma unroll
            for (int g = 0; g < 4; g++) { accA[g] = biasA[g]; accB[g] = biasB[g]; }
            #pragma unroll
            for (int g = 0; g < 4; g++) {
                #pragma unroll
                for (int s = 0; s < NKS; s++) {
                    const float* pp = g_part + (size_t)(s * NM + mg) * RPC * BATCH + pb;
                    accA[g] += __ldcg(pp + (size_t)(g * 32 + jlA) * BATCH);
                    accB[g] += __ldcg(pp + (size_t)(g * 32 + jlB) * BATCH);
                }
            }
            float f, i1, i2, o, hv;

            f = sigm(accA[0]); i1 = sigm(accA[1]); i2 = tanhf(accA[2]); o = sigm(accA[3]);
            cA = cA * f + i1 * i2;
            hv = tanhf(cA) * o;
            out[(size_t)t * BH + (size_t)pb * HID + jA] = hv;
            g_hh[hw + (size_t)pb * HID + jA] = __float2half_rn(hv);
            if (t == SEQ - 1) {
                out[SBH + (size_t)pb * HID + jA] = hv;
                out[SBH + BH + (size_t)pb * HID + jA] = cA;
            }

            f = sigm(accB[0]); i1 = sigm(accB[1]); i2 = tanhf(accB[2]); o = sigm(accB[3]);
            cB = cB * f + i1 * i2;
            hv = tanhf(cB) * o;
            out[(size_t)t * BH + (size_t)pb * HID + jB] = hv;
            g_hh[hw + (size_t)pb * HID + jB] = __float2half_rn(hv);
            if (t == SEQ - 1) {
                out[SBH + (size_t)pb * HID + jB] = hv;
                out[SBH + BH + (size_t)pb * HID + jB] = cB;
            }
        }

        if (t + 1 < SEQ) {
            // ---- ready signal: this group's pointwise(t) done ----
            __syncthreads();                 // h stores CTA-wide complete
            if (tid == 0) {
                __threadfence();             // release h stores
                atomicAdd(readyc, 1u);
            }
            // ---- dep-wait: 8 dep groups + self ready >= (t+1)*4 (parallel poll) ----
            if (tid >= 1 && tid <= 9) {
                const unsigned tgt = (unsigned)(t + 1) * NKS;
                while (*depc < tgt) __nanosleep(16);
                __threadfence();             // acquire
            }
            __syncthreads();

            // ---- stage h(t+1) from buf[(t+1)&1] ----
            const uint4* hs = (const uint4*)(g_hh + (size_t)((t + 1) & 1) * BH + hoff);
            #pragma unroll
            for (int q = 0; q < 8; q++)
                *(uint4*)(b_row + stf * 128 + q * 16) = __ldcg(hs + q);
            __syncthreads();
        }
    }
}

// ---------------------------------------------------------------------------
extern "C" void kernel_launch(void* const* d_in, const int* in_sizes, int n_in,
                              void* d_out, int out_size) {
    Params P;
    P.x = (const float*)d_in[0];
    P.Wx[0] = (const float*)d_in[1];  P.bx[0] = (const float*)d_in[2];
    P.Wx[1] = (const float*)d_in[3];  P.bx[1] = (const float*)d_in[4];
    P.Wx[2] = (const float*)d_in[5];  P.bx[2] = (const float*)d_in[6];
    P.Wx[3] = (const float*)d_in[7];  P.bx[3] = (const float*)d_in[8];
    P.Wh[0] = (const float*)d_in[9];  P.bh[0] = (const float*)d_in[10];
    P.Wh[1] = (const float*)d_in[11]; P.bh[1] = (const float*)d_in[12];
    P.Wh[2] = (const float*)d_in[13]; P.bh[2] = (const float*)d_in[14];
    P.Wh[3] = (const float*)d_in[15]; P.bh[3] = (const float*)d_in[16];
    P.out   = (float*)d_out;

    static bool attr_set = false;
    if (!attr_set) {
        cudaFuncSetAttribute(lstm_mma, cudaFuncAttributeMaxDynamicSharedMemorySize,
                             SMEM_TOTAL);
        attr_set = true;
    }

    init_kernel<<<(SEQ * BATCH * INPUT / 4 + 255) / 256, 256>>>(P.x);
    lstm_mma<<<NCTA, NTHR, SMEM_TOTAL>>>(P);
}